// round 16
// baseline (speedup 1.0000x reference)
#include <cuda_runtime.h>
#include <cstdint>

// ---------------------------------------------------------------------------
// LargeLoss via radix-select on RAW INPUT BITS (softplus is monotone, so the
// kth-largest unobserved loss == softplus(kth-largest x among t<0)).
// R16: output written in passB; finalize shrinks to a ~37k-element fixup.
//   passA : zero g_fine (+hist2 by block0); stream in+tg -> class codes +
//           smem hist of top-12 key bits -> g_hist1
//   passB : per-block select0 from hist1+k (publish mode/p1/k1); stream
//           in+codes -> LOSSES WRITTEN TO OUT; in-bucket cls==2 ->
//           hist2/fine atomics + record index in per-block region of g_didx
//   fixup : per-block select12 from hist2+fine -> thr; repair recorded
//           indices (out[idx] = nl<thr ? nl : 0); redo scalar tail with thr;
//           block0 zeroes hist1 for next replay
// ---------------------------------------------------------------------------

#define FINE_BINS (1u << 20)
#define N_MAXE 10240000
#define N_MAXQ (N_MAXE / 4 + 8)
#define GRID_N 1184

__device__ unsigned char g_code[N_MAXQ];          // 2 bits/elem, 1 byte per float4
__device__ unsigned g_hist1[4096];                // zeroed by fixup block 0
__device__ unsigned g_hist2[4096];                // zeroed by passA block 0
__device__ unsigned g_fine[FINE_BINS];            // zeroed by passA (grid)
__device__ unsigned g_didx[N_MAXE + 8];           // deferred indices, per-block regions
__device__ unsigned g_dcnt_blk[GRID_N];           // per-block deferred counts
__device__ unsigned g_k1;                         // published by passB
__device__ unsigned g_p1;                         // published by passB
__device__ int      g_mode;                       // published by passB

// ---------------------------------------------------------------------------
__device__ __forceinline__ unsigned f2key(float x) {
    unsigned b = __float_as_uint(x);
    return (b & 0x80000000u) ? ~b : (b | 0x80000000u);
}
__device__ __forceinline__ float key2f(unsigned k) {
    unsigned b = (k & 0x80000000u) ? (k & 0x7FFFFFFFu) : ~k;
    return __uint_as_float(b);
}
__device__ __forceinline__ float lse_fast(float ax) {
    return __logf(1.0f + __expf(-ax));
}
__device__ __forceinline__ float neg_loss_f(float x) {   // softplus(x)
    return fmaxf(x, 0.0f) + lse_fast(fabsf(x));
}
__device__ __forceinline__ unsigned warp_sufscan(unsigned v, int lane) {
#pragma unroll
    for (int d = 1; d < 32; d <<= 1) {
        unsigned u = __shfl_down_sync(0xffffffffu, v, d);
        if (lane + d < 32) v += u;
    }
    return v;
}
__device__ __forceinline__ float elem_loss_t(float x, float t, float thr) {
    float ax  = fabsf(x);
    float lse = lse_fast(ax);
    float r = 0.0f;
    if (t > 0.0f) r = fmaxf(-x, 0.0f) + lse;
    else if (t < 0.0f) {
        float nl = fmaxf(x, 0.0f) + lse;
        r = (nl < thr) ? nl : 0.0f;
    }
    return r;
}

// ---------------------------------------------------------------------------
// Pass A: zero scratch; stream in+tg (contiguous chunk) -> class codes +
// 12-bit key histogram. (Profiled form: ~21.5us, occ ~90%.)
__global__ void __launch_bounds__(256, 8)
passA_kernel(const float* __restrict__ in, const float* __restrict__ tg, int n) {
    __shared__ unsigned hist[4096];
    const int tid = threadIdx.x, bs = blockDim.x;
    for (int i = tid; i < 4096; i += bs) hist[i] = 0u;

    {
        const unsigned t = blockIdx.x * bs + tid;
        const unsigned S = gridDim.x * bs;
        uint4* f4 = (uint4*)g_fine;
        const unsigned M4 = FINE_BINS / 4;
        for (unsigned i = t; i < M4; i += S) f4[i] = make_uint4(0u, 0u, 0u, 0u);
    }
    if (blockIdx.x == 0) {
        for (int i = tid; i < 4096; i += bs) g_hist2[i] = 0u;
    }
    __syncthreads();

    const float4* in4 = (const float4*)in;
    const float4* tg4 = (const float4*)tg;
    const int n4 = n >> 2;
    const int per = (n4 + gridDim.x - 1) / gridDim.x;
    const int lo4 = blockIdx.x * per;
    const int hi4 = min(n4, lo4 + per);

#define CLS(tv) ((tv) < 0.f ? 2u : ((tv) > 0.f ? 1u : 0u))
#define CODEQ(tq) (unsigned char)(CLS((tq).x) | (CLS((tq).y) << 2) | \
                                  (CLS((tq).z) << 4) | (CLS((tq).w) << 6))
#define HISTQ(xq, tq) do {                                                   \
        if ((tq).x < 0.f) atomicAdd(&hist[f2key((xq).x) >> 20], 1u);         \
        if ((tq).y < 0.f) atomicAdd(&hist[f2key((xq).y) >> 20], 1u);         \
        if ((tq).z < 0.f) atomicAdd(&hist[f2key((xq).z) >> 20], 1u);         \
        if ((tq).w < 0.f) atomicAdd(&hist[f2key((xq).w) >> 20], 1u); } while (0)

    int i = lo4 + tid;
    for (; i + bs < hi4; i += 2 * bs) {
        float4 x0 = in4[i],      t0 = tg4[i];
        float4 x1 = in4[i + bs], t1 = tg4[i + bs];
        g_code[i]      = CODEQ(t0);
        g_code[i + bs] = CODEQ(t1);
        HISTQ(x0, t0);
        HISTQ(x1, t1);
    }
    for (; i < hi4; i += bs) {
        float4 x0 = in4[i], t0 = tg4[i];
        g_code[i] = CODEQ(t0);
        HISTQ(x0, t0);
    }
    if (blockIdx.x == 0) {
        for (int j = (n4 << 2) + tid; j < n; j += bs)
            if (tg[j] < 0.f) atomicAdd(&hist[f2key(in[j]) >> 20], 1u);
    }
#undef HISTQ
#undef CODEQ
#undef CLS

    __syncthreads();
    for (int i2 = tid; i2 < 4096; i2 += bs) {
        unsigned hv = hist[i2];
        if (hv) atomicAdd(&g_hist1[i2], hv);
    }
}

// ---------------------------------------------------------------------------
// Pass B: select0 per block, then stream in+codes -> losses -> out.
// In-bucket cls==2: hist2/fine atomics + defer index into per-block region.
__global__ void __launch_bounds__(256, 6)
passB_kernel(const float* __restrict__ in,
             const float* __restrict__ tg,
             const int* __restrict__ kptr,
             float* __restrict__ out, int n) {
    __shared__ unsigned hist[4096];
    __shared__ unsigned wsumA[8], wsufA[8];
    __shared__ unsigned s_p1, s_k1, s_dc;

    const int tid = threadIdx.x, bs = blockDim.x;   // bs == 256
    const int lane = tid & 31, wid = tid >> 5;

    // ---- per-block select0 over g_hist1 ----
    unsigned h[16]; unsigned sum = 0;
    {
        const uint4* h4 = (const uint4*)g_hist1;
#pragma unroll
        for (int j = 0; j < 4; j++) {
            uint4 q = h4[tid * 4 + j];
            h[j * 4 + 0] = q.x; h[j * 4 + 1] = q.y;
            h[j * 4 + 2] = q.z; h[j * 4 + 3] = q.w;
            sum += q.x + q.y + q.z + q.w;
        }
    }
    unsigned v = warp_sufscan(sum, lane);
    if (lane == 0) wsumA[wid] = v;
    if (tid == 0) { s_p1 = 0u; s_k1 = 0u; s_dc = 0u; }
    __syncthreads();
    if (tid < 8) {
        unsigned acc = 0;
        for (int j = tid + 1; j < 8; j++) acc += wsumA[j];
        wsufA[tid] = acc;
    }
    __syncthreads();
    const unsigned total = wsufA[0] + wsumA[0];
    int kraw = *kptr;
    const unsigned kk = (kraw > 0) ? (unsigned)kraw : 0u;
    const int mode = (kk == 0u) ? 1 : ((kk > total) ? 2 : 0);
    if (mode == 0) {
        unsigned run = v + wsufA[wid];
#pragma unroll
        for (int j = 0; j < 16; j++) {
            unsigned nxt = run - h[j];
            if (run >= kk && nxt < kk) { s_p1 = (unsigned)(tid * 16 + j); s_k1 = kk - nxt; }
            run = nxt;
        }
    }
    __syncthreads();
    if (tid == 0) { g_mode = mode; g_p1 = s_p1; g_k1 = s_k1; }
    for (int i = tid; i < 4096; i += bs) hist[i] = 0u;
    __syncthreads();

    const unsigned p1 = s_p1;
    const unsigned lo = p1 << 20;
    const float4* in4 = (const float4*)in;
    float4* o4 = (float4*)out;
    const int n4 = n >> 2;
    const int per = (n4 + gridDim.x - 1) / gridDim.x;
    const int lo4 = blockIdx.x * per;
    const int hi4 = min(n4, lo4 + per);
    const unsigned dbase = (unsigned)lo4 * 4u;

    if (mode == 0) {
        // normal path: three-way bucket decision, defer in-bucket
#define PBV(xv, cls, eidx, ov) do {                                          \
        float _ax = fabsf(xv);                                               \
        float _ls = lse_fast(_ax);                                           \
        float _o = 0.0f;                                                     \
        if ((cls) == 1u) _o = fmaxf(-(xv), 0.0f) + _ls;                      \
        else if ((cls) == 2u) {                                              \
            float _nl = fmaxf((xv), 0.0f) + _ls;                             \
            unsigned _key = f2key(xv);                                       \
            unsigned _b = _key >> 20;                                        \
            if (_b == p1) {                                                  \
                unsigned _d = _key - lo;                                     \
                atomicAdd(&hist[_d >> 8], 1u);                               \
                atomicAdd(&g_fine[_d], 1u);                                  \
                unsigned _off = atomicAdd(&s_dc, 1u);                        \
                g_didx[dbase + _off] = (eidx);                               \
                _o = _nl;                                                    \
            } else _o = (_b < p1) ? _nl : 0.0f;                              \
        }                                                                    \
        (ov) = _o; } while (0)
        for (int i = lo4 + tid; i < hi4; i += bs) {
            float4 x = in4[i];
            unsigned c = g_code[i];
            float4 o;
            unsigned e = (unsigned)i * 4u;
            PBV(x.x,  c        & 3u, e + 0u, o.x);
            PBV(x.y, (c >> 2)  & 3u, e + 1u, o.y);
            PBV(x.z, (c >> 4)  & 3u, e + 2u, o.z);
            PBV(x.w, (c >> 6)  & 3u, e + 3u, o.w);
            o4[i] = o;
        }
        // scalar tail: hist/fine only + provisional write (fixup redoes it)
        if (blockIdx.x == 0) {
            for (int j = (n4 << 2) + tid; j < n; j += bs) {
                float xv = in[j];
                float tv = tg[j];
                float ax = fabsf(xv);
                float ls = lse_fast(ax);
                float o = 0.0f;
                if (tv > 0.f) o = fmaxf(-xv, 0.0f) + ls;
                else if (tv < 0.f) {
                    float nl = fmaxf(xv, 0.0f) + ls;
                    unsigned key = f2key(xv);
                    unsigned b = key >> 20;
                    if (b == p1) {
                        unsigned d = key - lo;
                        atomicAdd(&hist[d >> 8], 1u);
                        atomicAdd(&g_fine[d], 1u);
                        o = nl;             // provisional; fixup finalizes
                    } else o = (b < p1) ? nl : 0.0f;
                }
                out[j] = o;
            }
        }
#undef PBV
        __syncthreads();
        for (int i2 = tid; i2 < 4096; i2 += bs) {
            unsigned hv = hist[i2];
            if (hv) atomicAdd(&g_hist2[i2], hv);
        }
        if (tid == 0) g_dcnt_blk[blockIdx.x] = s_dc;
    } else {
        // mode 1: keep all negs; mode 2: drop all negs. No deferral.
        const float thr = (mode == 1) ? __int_as_float(0x7f800000) : 0.0f;
        for (int i = lo4 + tid; i < hi4; i += bs) {
            float4 x = in4[i];
            unsigned c = g_code[i];
            float4 o;
            {
                float ax = fabsf(x.x); float ls = lse_fast(ax);
                unsigned cl = c & 3u;
                o.x = (cl == 1u) ? fmaxf(-x.x, 0.f) + ls
                    : (cl == 2u ? ((fmaxf(x.x, 0.f) + ls) < thr ? fmaxf(x.x, 0.f) + ls : 0.f) : 0.f);
            }
            {
                float ax = fabsf(x.y); float ls = lse_fast(ax);
                unsigned cl = (c >> 2) & 3u;
                o.y = (cl == 1u) ? fmaxf(-x.y, 0.f) + ls
                    : (cl == 2u ? ((fmaxf(x.y, 0.f) + ls) < thr ? fmaxf(x.y, 0.f) + ls : 0.f) : 0.f);
            }
            {
                float ax = fabsf(x.z); float ls = lse_fast(ax);
                unsigned cl = (c >> 4) & 3u;
                o.z = (cl == 1u) ? fmaxf(-x.z, 0.f) + ls
                    : (cl == 2u ? ((fmaxf(x.z, 0.f) + ls) < thr ? fmaxf(x.z, 0.f) + ls : 0.f) : 0.f);
            }
            {
                float ax = fabsf(x.w); float ls = lse_fast(ax);
                unsigned cl = (c >> 6) & 3u;
                o.w = (cl == 1u) ? fmaxf(-x.w, 0.f) + ls
                    : (cl == 2u ? ((fmaxf(x.w, 0.f) + ls) < thr ? fmaxf(x.w, 0.f) + ls : 0.f) : 0.f);
            }
            o4[i] = o;
        }
        if (blockIdx.x == 0) {
            for (int j = (n4 << 2) + tid; j < n; j += bs)
                out[j] = elem_loss_t(in[j], tg[j], thr);
        }
    }
}

// ---------------------------------------------------------------------------
// Fixup: per-block select12 (hist2 + fine -> thr), repair deferred indices,
// redo scalar tail exactly. Block 0 zeroes hist1 for next replay.
__global__ void fixup_kernel(const float* __restrict__ in,
                             const float* __restrict__ tg,
                             float* __restrict__ out, int n) {
    __shared__ unsigned wsumB[8], wsufB[8];
    __shared__ unsigned s_bin, s_krem;
    __shared__ float s_thr;

    const int tid = threadIdx.x, bs = blockDim.x;   // bs == 256
    const int lane = tid & 31, wid = tid >> 5;
    const int mode = g_mode;

    // reset replay state
    if (blockIdx.x == 0) {
        for (int i = tid; i < 4096; i += bs) g_hist1[i] = 0u;
    }

    if (mode != 0) return;   // passB already wrote exact outputs (incl. tail)

    const unsigned k1 = g_k1;
    const unsigned p1 = g_p1;
    // coarse select over g_hist2
    unsigned h[16]; unsigned sum = 0;
    {
        const uint4* h4 = (const uint4*)g_hist2;
#pragma unroll
        for (int j = 0; j < 4; j++) {
            uint4 q = h4[tid * 4 + j];
            h[j * 4 + 0] = q.x; h[j * 4 + 1] = q.y;
            h[j * 4 + 2] = q.z; h[j * 4 + 3] = q.w;
            sum += q.x + q.y + q.z + q.w;
        }
    }
    unsigned v = warp_sufscan(sum, lane);
    if (lane == 0) wsumB[wid] = v;
    if (tid == 0) { s_bin = 0u; s_krem = 1u; }
    __syncthreads();
    if (tid < 8) {
        unsigned acc = 0;
        for (int j = tid + 1; j < 8; j++) acc += wsumB[j];
        wsufB[tid] = acc;
    }
    __syncthreads();
    {
        unsigned run = v + wsufB[wid];
#pragma unroll
        for (int j = 0; j < 16; j++) {
            unsigned nxt = run - h[j];
            if (run >= k1 && nxt < k1) { s_bin = (unsigned)(tid * 16 + j); s_krem = k1 - nxt; }
            run = nxt;
        }
    }
    __syncthreads();
    // fine select over 256 bins of coarse bin s_bin
    const unsigned b2 = s_bin;
    const unsigned krem = s_krem;
    unsigned fh = g_fine[(b2 << 8) | (unsigned)tid];
    unsigned fv = warp_sufscan(fh, lane);
    if (lane == 0) wsumB[wid] = fv;
    __syncthreads();
    if (tid < 8) {
        unsigned acc = 0;
        for (int j = tid + 1; j < 8; j++) acc += wsumB[j];
        wsufB[tid] = acc;
    }
    __syncthreads();
    {
        unsigned fsfx = fv + wsufB[wid];
        unsigned nxt = fsfx - fh;
        if (fsfx >= krem && nxt < krem)
            s_thr = neg_loss_f(key2f((p1 << 20) | (b2 << 8) | (unsigned)tid));
    }
    __syncthreads();
    const float thr = s_thr;

    // repair this block's deferred region
    const int n4 = n >> 2;
    const int per = (n4 + gridDim.x - 1) / gridDim.x;
    const unsigned dbase = (unsigned)(blockIdx.x * per) * 4u;
    const unsigned cnt = g_dcnt_blk[blockIdx.x];
    for (unsigned j = tid; j < cnt; j += bs) {
        unsigned idx = g_didx[dbase + j];
        float x = in[idx];
        float nl = neg_loss_f(x);
        out[idx] = (nl < thr) ? nl : 0.0f;
    }
    // redo scalar tail exactly with thr
    if (blockIdx.x == 0) {
        for (int j = (n4 << 2) + tid; j < n; j += bs)
            out[j] = elem_loss_t(in[j], tg[j], thr);
    }
}

// ---------------------------------------------------------------------------
extern "C" void kernel_launch(void* const* d_in, const int* in_sizes, int n_in,
                              void* d_out, int out_size) {
    const float* inp  = (const float*)d_in[0];
    const float* tgt  = (const float*)d_in[1];
    const int*   kptr = (const int*)d_in[2];
    float* out = (float*)d_out;
    const int n = in_sizes[0];

    passA_kernel<<<GRID_N, 256>>>(inp, tgt, n);
    passB_kernel<<<GRID_N, 256>>>(inp, tgt, kptr, out, n);
    fixup_kernel<<<GRID_N, 256>>>(inp, tgt, out, n);
}

// round 17
// speedup vs baseline: 1.1136x; 1.1136x over previous
#include <cuda_runtime.h>
#include <cstdint>

// ---------------------------------------------------------------------------
// LargeLoss via radix-select on RAW INPUT BITS (softplus is monotone, so the
// kth-largest unobserved loss == softplus(kth-largest x among t<0)).
// R17 = R12 (best measured: 53.7us). 3 lean streaming kernels:
//   passA    : zero g_fine (+hist2 by block0); stream in+tg -> class codes +
//              smem hist of top-12 key bits -> g_hist1
//   passB    : per-block select0 from hist1+k (publish mode/p1/k1); stream
//              in+codes; cls==2 & in-bucket -> smem hist2[d>>8] + g_fine[d]
//   finalize : per-block select12 from hist2+fine -> thr; stream in+codes ->
//              losses; block0 zeroes hist1 for next replay
// ---------------------------------------------------------------------------

#define FINE_BINS (1u << 20)
#define N_MAXQ (10240000 / 4 + 8)

__device__ unsigned char g_code[N_MAXQ];          // 2 bits/elem, 1 byte per float4
__device__ unsigned g_hist1[4096];                // zeroed by finalize block 0
__device__ unsigned g_hist2[4096];                // zeroed by passA block 0
__device__ unsigned g_fine[FINE_BINS];            // zeroed by passA (grid)
__device__ unsigned g_k1;                         // published by passB
__device__ unsigned g_p1;                         // published by passB
__device__ int      g_mode;                       // published by passB

// ---------------------------------------------------------------------------
__device__ __forceinline__ unsigned f2key(float x) {
    unsigned b = __float_as_uint(x);
    return (b & 0x80000000u) ? ~b : (b | 0x80000000u);
}
__device__ __forceinline__ float key2f(unsigned k) {
    unsigned b = (k & 0x80000000u) ? (k & 0x7FFFFFFFu) : ~k;
    return __uint_as_float(b);
}
// fast softplus pieces: lse = log(1 + e^-|x|), via MUFU intrinsics.
__device__ __forceinline__ float lse_fast(float ax) {
    return __logf(1.0f + __expf(-ax));
}
__device__ __forceinline__ float neg_loss_f(float x) {   // softplus(x)
    return fmaxf(x, 0.0f) + lse_fast(fabsf(x));
}
// inclusive suffix scan within a warp
__device__ __forceinline__ unsigned warp_sufscan(unsigned v, int lane) {
#pragma unroll
    for (int d = 1; d < 32; d <<= 1) {
        unsigned u = __shfl_down_sync(0xffffffffu, v, d);
        if (lane + d < 32) v += u;
    }
    return v;
}

// ---------------------------------------------------------------------------
// Pass A: zero scratch; stream in+tg -> class codes + 12-bit key histogram.
__global__ void passA_kernel(const float* __restrict__ in,
                             const float* __restrict__ tg, int n) {
    __shared__ unsigned hist[4096];
    const int tid = threadIdx.x, bs = blockDim.x;
    for (int i = tid; i < 4096; i += bs) hist[i] = 0u;

    // zero g_fine (grid) and g_hist2 (block 0) for this replay
    {
        const unsigned t = blockIdx.x * bs + tid;
        const unsigned S = gridDim.x * bs;
        uint4* f4 = (uint4*)g_fine;
        const unsigned M4 = FINE_BINS / 4;
        for (unsigned i = t; i < M4; i += S) f4[i] = make_uint4(0u, 0u, 0u, 0u);
    }
    if (blockIdx.x == 0) {
        for (int i = tid; i < 4096; i += bs) g_hist2[i] = 0u;
    }
    __syncthreads();

    const float4* in4 = (const float4*)in;
    const float4* tg4 = (const float4*)tg;
    const int n4 = n >> 2;
    const int S = gridDim.x * bs;
    int i = blockIdx.x * bs + tid;

#define CLS(tv) ((tv) < 0.f ? 2u : ((tv) > 0.f ? 1u : 0u))
#define HISTQ(xq, tq) do {                                                   \
        if ((tq).x < 0.f) atomicAdd(&hist[f2key((xq).x) >> 20], 1u);         \
        if ((tq).y < 0.f) atomicAdd(&hist[f2key((xq).y) >> 20], 1u);         \
        if ((tq).z < 0.f) atomicAdd(&hist[f2key((xq).z) >> 20], 1u);         \
        if ((tq).w < 0.f) atomicAdd(&hist[f2key((xq).w) >> 20], 1u); } while (0)

    for (; i + S < n4; i += 2 * S) {
        float4 x0 = in4[i],     t0 = tg4[i];
        float4 x1 = in4[i + S], t1 = tg4[i + S];
        g_code[i]     = (unsigned char)(CLS(t0.x) | (CLS(t0.y) << 2) |
                                        (CLS(t0.z) << 4) | (CLS(t0.w) << 6));
        g_code[i + S] = (unsigned char)(CLS(t1.x) | (CLS(t1.y) << 2) |
                                        (CLS(t1.z) << 4) | (CLS(t1.w) << 6));
        HISTQ(x0, t0);
        HISTQ(x1, t1);
    }
    for (; i < n4; i += S) {
        float4 x0 = in4[i], t0 = tg4[i];
        g_code[i] = (unsigned char)(CLS(t0.x) | (CLS(t0.y) << 2) |
                                    (CLS(t0.z) << 4) | (CLS(t0.w) << 6));
        HISTQ(x0, t0);
    }
    // scalar tail (n % 4), block 0: histogram only (finalize tail uses tg)
    if (blockIdx.x == 0) {
        for (int j = (n4 << 2) + tid; j < n; j += bs)
            if (tg[j] < 0.f) atomicAdd(&hist[f2key(in[j]) >> 20], 1u);
    }
#undef HISTQ
#undef CLS

    __syncthreads();
    for (int i2 = tid; i2 < 4096; i2 += bs) {
        unsigned hv = hist[i2];
        if (hv) atomicAdd(&g_hist1[i2], hv);
    }
}

// ---------------------------------------------------------------------------
// Pass B: per-block select0 (hist1 + k -> p1, k1, mode; publish), then stream
// in+codes: cls==2 & in-bucket -> smem hist2[d>>8] + global fine[d].
__global__ void passB_kernel(const float* __restrict__ in,
                             const float* __restrict__ tg,
                             const int* __restrict__ kptr, int n) {
    __shared__ unsigned hist[4096];
    __shared__ unsigned wsumA[8], wsufA[8];
    __shared__ unsigned s_p1, s_k1;

    const int tid = threadIdx.x, bs = blockDim.x;   // bs == 256
    const int lane = tid & 31, wid = tid >> 5;

    // ---- per-block select0 over g_hist1 (16 bins per thread) ----
    unsigned h[16]; unsigned sum = 0;
    {
        const uint4* h4 = (const uint4*)g_hist1;
#pragma unroll
        for (int j = 0; j < 4; j++) {
            uint4 q = h4[tid * 4 + j];
            h[j * 4 + 0] = q.x; h[j * 4 + 1] = q.y;
            h[j * 4 + 2] = q.z; h[j * 4 + 3] = q.w;
            sum += q.x + q.y + q.z + q.w;
        }
    }
    unsigned v = warp_sufscan(sum, lane);
    if (lane == 0) wsumA[wid] = v;
    if (tid == 0) { s_p1 = 0u; s_k1 = 0u; }
    __syncthreads();
    if (tid < 8) {
        unsigned acc = 0;
        for (int j = tid + 1; j < 8; j++) acc += wsumA[j];
        wsufA[tid] = acc;
    }
    __syncthreads();
    const unsigned total = wsufA[0] + wsumA[0];
    int kraw = *kptr;
    const unsigned kk = (kraw > 0) ? (unsigned)kraw : 0u;
    const int mode = (kk == 0u) ? 1 : ((kk > total) ? 2 : 0);
    if (mode == 0) {
        unsigned run = v + wsufA[wid];
#pragma unroll
        for (int j = 0; j < 16; j++) {
            unsigned nxt = run - h[j];
            if (run >= kk && nxt < kk) { s_p1 = (unsigned)(tid * 16 + j); s_k1 = kk - nxt; }
            run = nxt;
        }
    }
    __syncthreads();
    if (tid == 0) { g_mode = mode; g_p1 = s_p1; g_k1 = s_k1; }  // identical in all blocks
    if (mode != 0) return;   // hist2/fine stay zero; finalize shortcuts on mode

    // ---- main scan over in + codes ----
    for (int i = tid; i < 4096; i += bs) hist[i] = 0u;
    __syncthreads();

    const unsigned lo = s_p1 << 20;   // bucket base in key space
    const float4* in4 = (const float4*)in;
    const int n4 = n >> 2;
    const int S = gridDim.x * bs;
    int i = blockIdx.x * bs + tid;

#define PB(xv, cq, sh) do {                                                  \
        if ((((cq) >> (sh)) & 3u) == 2u) {                                   \
            unsigned _dv = f2key(xv) - lo;                                   \
            if (_dv < 0x100000u) {                                           \
                atomicAdd(&hist[_dv >> 8], 1u);                              \
                atomicAdd(&g_fine[_dv], 1u);                                 \
            } } } while (0)
#define PBQ(xq, cq) do { PB((xq).x, cq, 0); PB((xq).y, cq, 2);               \
                         PB((xq).z, cq, 4); PB((xq).w, cq, 6); } while (0)
    for (; i + S < n4; i += 2 * S) {
        float4 x0 = in4[i],     x1 = in4[i + S];
        unsigned c0 = g_code[i], c1 = g_code[i + S];
        PBQ(x0, c0);
        PBQ(x1, c1);
    }
    for (; i < n4; i += S) {
        float4 x0 = in4[i];
        unsigned c0 = g_code[i];
        PBQ(x0, c0);
    }
    if (blockIdx.x == 0) {
        for (int j = (n4 << 2) + tid; j < n; j += bs) {
            if (tg[j] < 0.f) {
                unsigned dv = f2key(in[j]) - lo;
                if (dv < 0x100000u) {
                    atomicAdd(&hist[dv >> 8], 1u);
                    atomicAdd(&g_fine[dv], 1u);
                }
            }
        }
    }
#undef PBQ
#undef PB
    __syncthreads();
    for (int i2 = tid; i2 < 4096; i2 += bs) {
        unsigned hv = hist[i2];
        if (hv) atomicAdd(&g_hist2[i2], hv);
    }
}

// ---------------------------------------------------------------------------
__device__ __forceinline__ float lane_loss(float x, unsigned cls, float thr) {
    float ax  = fabsf(x);
    float lse = lse_fast(ax);
    float pl  = fmaxf(-x, 0.0f) + lse;
    float nl  = fmaxf( x, 0.0f) + lse;
    float r = 0.0f;
    if (cls == 1u) r = pl;
    else if (cls == 2u) r = (nl < thr) ? nl : 0.0f;
    return r;
}
__device__ __forceinline__ float elem_loss_t(float x, float t, float thr) {
    unsigned cls = (t > 0.f) ? 1u : ((t < 0.f) ? 2u : 0u);
    return lane_loss(x, cls, thr);
}

// Finalize: per-block select12 (hist2 + fine -> threshold), then stream.
// Block 0 also re-zeroes hist1 for the next replay.
__global__ void finalize_kernel(const float* __restrict__ in,
                                const float* __restrict__ tg,
                                float* __restrict__ out, int n) {
    __shared__ unsigned wsumB[8], wsufB[8];
    __shared__ unsigned s_bin, s_krem;
    __shared__ float s_thr;

    const int tid = threadIdx.x, bs = blockDim.x;   // bs == 256
    const int lane = tid & 31, wid = tid >> 5;
    const int mode = g_mode;

    float thr;
    if (mode == 1)      thr = __int_as_float(0x7f800000);  // keep all
    else if (mode == 2) thr = 0.0f;                        // drop all negs
    else {
        const unsigned k1 = g_k1;
        const unsigned p1 = g_p1;
        // coarse select over g_hist2 (16 bins per thread)
        unsigned h[16]; unsigned sum = 0;
        {
            const uint4* h4 = (const uint4*)g_hist2;
#pragma unroll
            for (int j = 0; j < 4; j++) {
                uint4 q = h4[tid * 4 + j];
                h[j * 4 + 0] = q.x; h[j * 4 + 1] = q.y;
                h[j * 4 + 2] = q.z; h[j * 4 + 3] = q.w;
                sum += q.x + q.y + q.z + q.w;
            }
        }
        unsigned v = warp_sufscan(sum, lane);
        if (lane == 0) wsumB[wid] = v;
        if (tid == 0) { s_bin = 0u; s_krem = 1u; }
        __syncthreads();
        if (tid < 8) {
            unsigned acc = 0;
            for (int j = tid + 1; j < 8; j++) acc += wsumB[j];
            wsufB[tid] = acc;
        }
        __syncthreads();
        {
            unsigned run = v + wsufB[wid];
#pragma unroll
            for (int j = 0; j < 16; j++) {
                unsigned nxt = run - h[j];
                if (run >= k1 && nxt < k1) { s_bin = (unsigned)(tid * 16 + j); s_krem = k1 - nxt; }
                run = nxt;
            }
        }
        __syncthreads();
        // fine select over 256 bins of coarse bin s_bin (1 per thread)
        const unsigned b2 = s_bin;
        const unsigned krem = s_krem;
        unsigned fh = g_fine[(b2 << 8) | (unsigned)tid];
        unsigned fv = warp_sufscan(fh, lane);
        if (lane == 0) wsumB[wid] = fv;
        __syncthreads();
        if (tid < 8) {
            unsigned acc = 0;
            for (int j = tid + 1; j < 8; j++) acc += wsumB[j];
            wsufB[tid] = acc;
        }
        __syncthreads();
        {
            unsigned fsfx = fv + wsufB[wid];
            unsigned nxt = fsfx - fh;
            if (fsfx >= krem && nxt < krem)
                s_thr = neg_loss_f(key2f((p1 << 20) | (b2 << 8) | (unsigned)tid));
        }
        __syncthreads();
        thr = s_thr;
    }

    // reset replay state (nothing reads hist1 after passB)
    if (blockIdx.x == 0) {
        for (int i = tid; i < 4096; i += bs) g_hist1[i] = 0u;
    }

    const float4* in4 = (const float4*)in;
    float4* o4 = (float4*)out;
    const int n4 = n >> 2;
    const int S = gridDim.x * bs;
    int i = blockIdx.x * bs + tid;

    for (; i + S < n4; i += 2 * S) {
        float4 x0 = in4[i];
        float4 x1 = in4[i + S];
        unsigned c0 = g_code[i];
        unsigned c1 = g_code[i + S];
        float4 o0, o1;
        o0.x = lane_loss(x0.x,  c0        & 3u, thr);
        o0.y = lane_loss(x0.y, (c0 >> 2)  & 3u, thr);
        o0.z = lane_loss(x0.z, (c0 >> 4)  & 3u, thr);
        o0.w = lane_loss(x0.w, (c0 >> 6)  & 3u, thr);
        o1.x = lane_loss(x1.x,  c1        & 3u, thr);
        o1.y = lane_loss(x1.y, (c1 >> 2)  & 3u, thr);
        o1.z = lane_loss(x1.z, (c1 >> 4)  & 3u, thr);
        o1.w = lane_loss(x1.w, (c1 >> 6)  & 3u, thr);
        o4[i] = o0;
        o4[i + S] = o1;
    }
    for (; i < n4; i += S) {
        float4 x0 = in4[i];
        unsigned c0 = g_code[i];
        float4 o0;
        o0.x = lane_loss(x0.x,  c0        & 3u, thr);
        o0.y = lane_loss(x0.y, (c0 >> 2)  & 3u, thr);
        o0.z = lane_loss(x0.z, (c0 >> 4)  & 3u, thr);
        o0.w = lane_loss(x0.w, (c0 >> 6)  & 3u, thr);
        o4[i] = o0;
    }
    if (blockIdx.x == 0) {
        for (int j = (n4 << 2) + tid; j < n; j += bs)
            out[j] = elem_loss_t(in[j], tg[j], thr);
    }
}

// ---------------------------------------------------------------------------
extern "C" void kernel_launch(void* const* d_in, const int* in_sizes, int n_in,
                              void* d_out, int out_size) {
    const float* inp  = (const float*)d_in[0];
    const float* tgt  = (const float*)d_in[1];
    const int*   kptr = (const int*)d_in[2];
    float* out = (float*)d_out;
    const int n = in_sizes[0];

    passA_kernel<<<1184, 256>>>(inp, tgt, n);
    passB_kernel<<<1184, 256>>>(inp, tgt, kptr, n);
    finalize_kernel<<<1184, 256>>>(inp, tgt, out, n);
}